// round 1
// baseline (speedup 1.0000x reference)
#include <cuda_runtime.h>
#include <math.h>

#define T_   1024
#define B_   8
#define E_   1024
#define H_   16
#define HD   64
#define NB   4
#define DIN  256
#define TOPK 16
#define ROWS (T_*B_)          // 8192
#define BE   (B_*E_)          // 8192
#define SCALING 0.125f        // 64^-0.5

// ---------- scratch (device globals; no runtime allocation) ----------
__device__ float g_q[ROWS * E_];
__device__ float g_k[ROWS * E_];
__device__ float g_v[ROWS * E_];
__device__ float g_ctx[ROWS * E_];

// =====================================================================
// Block-diagonal group GEMM:  Y[:, nb*256:(nb+1)*256] = X[:, nb*256:] @ W[nb] + b[nb], * scale
// BM=128, BN=128, BK=8, 256 threads, 8x8 microtile.
// grid = (ROWS/128, DIN/128, NB)
// =====================================================================
__global__ void __launch_bounds__(256) group_gemm(
    const float* __restrict__ X, const float* __restrict__ W,
    const float* __restrict__ bias, float* __restrict__ Y, float scale)
{
    const int nb = blockIdx.z;
    const int m0 = blockIdx.x * 128;
    const int n0 = blockIdx.y * 128;
    const float* Wn = W + nb * DIN * DIN;

    __shared__ float As[8][128];
    __shared__ float Bs[8][128];

    const int tid = threadIdx.x;
    const int ty = tid >> 4;          // 0..15 -> rows
    const int tx = tid & 15;          // 0..15 -> cols

    const int arow = tid >> 1;        // 0..127
    const int akc  = (tid & 1) * 4;   // 0 or 4
    const int bkr  = tid >> 5;        // 0..7
    const int bcol = (tid & 31) * 4;  // 0..124

    const float* Xb = X + (long)m0 * E_ + nb * DIN;

    float acc[8][8];
#pragma unroll
    for (int i = 0; i < 8; i++)
#pragma unroll
        for (int j = 0; j < 8; j++) acc[i][j] = 0.0f;

    for (int k0 = 0; k0 < DIN; k0 += 8) {
        float4 a4 = *(const float4*)(Xb + (long)arow * E_ + k0 + akc);
        float4 b4 = *(const float4*)(Wn + (k0 + bkr) * DIN + n0 + bcol);
        As[akc + 0][arow] = a4.x;
        As[akc + 1][arow] = a4.y;
        As[akc + 2][arow] = a4.z;
        As[akc + 3][arow] = a4.w;
        *(float4*)&Bs[bkr][bcol] = b4;
        __syncthreads();

#pragma unroll
        for (int kk = 0; kk < 8; kk++) {
            float af[8], bf[8];
            *(float4*)(af)     = *(const float4*)&As[kk][ty * 8];
            *(float4*)(af + 4) = *(const float4*)&As[kk][ty * 8 + 4];
            *(float4*)(bf)     = *(const float4*)&Bs[kk][tx * 8];
            *(float4*)(bf + 4) = *(const float4*)&Bs[kk][tx * 8 + 4];
#pragma unroll
            for (int i = 0; i < 8; i++)
#pragma unroll
                for (int j = 0; j < 8; j++)
                    acc[i][j] = fmaf(af[i], bf[j], acc[i][j]);
        }
        __syncthreads();
    }

    // epilogue: bias + scale, vectorized stores
    float bj[8];
#pragma unroll
    for (int j = 0; j < 8; j++) bj[j] = bias[nb * DIN + n0 + tx * 8 + j];

#pragma unroll
    for (int i = 0; i < 8; i++) {
        const long row = m0 + ty * 8 + i;
        float* yp = Y + row * E_ + nb * DIN + n0 + tx * 8;
        float4 o0, o1;
        o0.x = (acc[i][0] + bj[0]) * scale;
        o0.y = (acc[i][1] + bj[1]) * scale;
        o0.z = (acc[i][2] + bj[2]) * scale;
        o0.w = (acc[i][3] + bj[3]) * scale;
        o1.x = (acc[i][4] + bj[4]) * scale;
        o1.y = (acc[i][5] + bj[5]) * scale;
        o1.z = (acc[i][6] + bj[6]) * scale;
        o1.w = (acc[i][7] + bj[7]) * scale;
        *(float4*)yp       = o0;
        *(float4*)(yp + 4) = o1;
    }
}

// =====================================================================
// Fused attention: scores -> softmax stats -> top-16 -> sparse ctx.
// One block = (32 queries) x (one of 128 batch-heads). 256 threads.
// Full 32x1024 score matrix kept in smem; top-16 of scores == top-16 of
// post-softmax probs (softmax is monotone); denominator over all keys.
// =====================================================================
#define QT  32
#define KT  256
#define SP  1032   // padded score row stride (floats)
#define KSP 65     // padded k/q tile row stride

__global__ void __launch_bounds__(256) attn_kernel(
    const float* __restrict__ qg, const float* __restrict__ kg,
    const float* __restrict__ vg, float* __restrict__ ctxg)
{
    extern __shared__ float sm[];
    float* S    = sm;                    // QT*SP
    float* ks   = S + QT * SP;           // KT*KSP
    float* qs   = ks + KT * KSP;         // QT*KSP
    float* rmax = qs + QT * KSP;         // 32
    float* rsum = rmax + QT;             // 32
    float* tpp  = rsum + QT;             // 32*16 probs
    int*   tpi  = (int*)(tpp + QT * TOPK); // 32*16 indices

    const int tid = threadIdx.x;
    const int qt  = blockIdx.x;          // 0..31
    const int bh  = blockIdx.y;          // 0..127
    const int bb  = bh >> 4;             // batch
    const int hh  = bh & 15;             // head
    const long base = (long)bb * E_ + hh * HD;

    // ---- load q tile (32 x 64) ----
    for (int f = tid; f < QT * 16; f += 256) {
        int r = f >> 4, d4 = (f & 15) * 4;
        float4 v4 = *(const float4*)(qg + (long)(qt * QT + r) * BE + base + d4);
        qs[r * KSP + d4 + 0] = v4.x;
        qs[r * KSP + d4 + 1] = v4.y;
        qs[r * KSP + d4 + 2] = v4.z;
        qs[r * KSP + d4 + 3] = v4.w;
    }

    // ---- scores: 32 x 1024 ----
    const int tq = tid >> 5;             // warp id: queries tq*4..+3
    const int tk = tid & 31;             // keys tk + 32*j (interleaved, bank-safe)

    for (int kt = 0; kt < T_; kt += KT) {
        __syncthreads();
        for (int f = tid; f < KT * 16; f += 256) {
            int r = f >> 4, d4 = (f & 15) * 4;
            float4 v4 = *(const float4*)(kg + (long)(kt + r) * BE + base + d4);
            ks[r * KSP + d4 + 0] = v4.x;
            ks[r * KSP + d4 + 1] = v4.y;
            ks[r * KSP + d4 + 2] = v4.z;
            ks[r * KSP + d4 + 3] = v4.w;
        }
        __syncthreads();

        float acc[4][8];
#pragma unroll
        for (int i = 0; i < 4; i++)
#pragma unroll
            for (int j = 0; j < 8; j++) acc[i][j] = 0.0f;

#pragma unroll 8
        for (int d = 0; d < HD; d++) {
            float qv[4];
#pragma unroll
            for (int i = 0; i < 4; i++) qv[i] = qs[(tq * 4 + i) * KSP + d];
#pragma unroll
            for (int j = 0; j < 8; j++) {
                float kv = ks[(tk + 32 * j) * KSP + d];
#pragma unroll
                for (int i = 0; i < 4; i++)
                    acc[i][j] = fmaf(qv[i], kv, acc[i][j]);
            }
        }
#pragma unroll
        for (int i = 0; i < 4; i++)
#pragma unroll
            for (int j = 0; j < 8; j++)
                S[(tq * 4 + i) * SP + kt + tk + 32 * j] = acc[i][j];
    }
    __syncthreads();

    // ---- softmax stats per row (warp w owns rows 4w..4w+3) ----
    const int w = tid >> 5, lane = tid & 31;
    for (int r = w * 4; r < w * 4 + 4; r++) {
        float m = -INFINITY;
#pragma unroll 8
        for (int t = 0; t < 32; t++) m = fmaxf(m, S[r * SP + lane + 32 * t]);
#pragma unroll
        for (int o = 16; o; o >>= 1) m = fmaxf(m, __shfl_xor_sync(~0u, m, o));
        float s = 0.0f;
#pragma unroll 8
        for (int t = 0; t < 32; t++) s += __expf(S[r * SP + lane + 32 * t] - m);
#pragma unroll
        for (int o = 16; o; o >>= 1) s += __shfl_xor_sync(~0u, s, o);
        if (lane == 0) { rmax[r] = m; rsum[r] = s; }
    }
    __syncwarp();

    // ---- top-16 per row: warp argmax with lazy per-lane cached max ----
    for (int r = w * 4; r < w * 4 + 4; r++) {
        const float m = rmax[r];
        const float inv = 1.0f / rsum[r];
        float lmax = -INFINITY; int lpos = lane;
#pragma unroll 8
        for (int t = 0; t < 32; t++) {
            float v = S[r * SP + lane + 32 * t];
            if (v > lmax) { lmax = v; lpos = lane + 32 * t; }
        }
        for (int it = 0; it < TOPK; it++) {
            float bm = lmax; int bp = lpos;
#pragma unroll
            for (int o = 16; o; o >>= 1) {
                float m2 = __shfl_xor_sync(~0u, bm, o);
                int   p2 = __shfl_xor_sync(~0u, bp, o);
                if (m2 > bm || (m2 == bm && p2 < bp)) { bm = m2; bp = p2; }
            }
            if (lane == 0) {
                tpi[r * TOPK + it] = bp;
                tpp[r * TOPK + it] = __expf(bm - m) * inv;
            }
            if ((bp & 31) == lane) {   // winner lane removes + rescans its 32
                S[r * SP + bp] = -INFINITY;
                lmax = -INFINITY; lpos = lane;
#pragma unroll 8
                for (int t = 0; t < 32; t++) {
                    float v = S[r * SP + lane + 32 * t];
                    if (v > lmax) { lmax = v; lpos = lane + 32 * t; }
                }
            }
        }
    }
    __syncthreads();

    // ---- sparse ctx: 16-key gather per query row ----
    const int cr = tid >> 3;             // 0..31 query row
    const int d0 = (tid & 7) * 8;        // 0..56
    float c[8];
#pragma unroll
    for (int i = 0; i < 8; i++) c[i] = 0.0f;
#pragma unroll
    for (int i = 0; i < TOPK; i++) {
        const int   idx = tpi[cr * TOPK + i];
        const float p   = tpp[cr * TOPK + i];
        const float* vp = vg + (long)idx * BE + base + d0;
        float4 a = *(const float4*)vp;
        float4 bq = *(const float4*)(vp + 4);
        c[0] = fmaf(p, a.x,  c[0]); c[1] = fmaf(p, a.y,  c[1]);
        c[2] = fmaf(p, a.z,  c[2]); c[3] = fmaf(p, a.w,  c[3]);
        c[4] = fmaf(p, bq.x, c[4]); c[5] = fmaf(p, bq.y, c[5]);
        c[6] = fmaf(p, bq.z, c[6]); c[7] = fmaf(p, bq.w, c[7]);
    }
    float* op = ctxg + (long)(qt * QT + cr) * BE + base + d0;
    *(float4*)op       = make_float4(c[0], c[1], c[2], c[3]);
    *(float4*)(op + 4) = make_float4(c[4], c[5], c[6], c[7]);
}

// =====================================================================
// launch
// =====================================================================
static const size_t ATTN_SMEM =
    (size_t)(QT * SP + KT * KSP + QT * KSP + QT + QT + QT * TOPK + QT * TOPK) * 4;

extern "C" void kernel_launch(void* const* d_in, const int* in_sizes, int n_in,
                              void* d_out, int out_size)
{
    const float* query  = (const float*)d_in[0];
    const float* key_in = (const float*)d_in[1];
    const float* value  = (const float*)d_in[2];
    const float* Wq = (const float*)d_in[3];
    const float* bq = (const float*)d_in[4];
    const float* Wk = (const float*)d_in[5];
    const float* bk = (const float*)d_in[6];
    const float* Wv = (const float*)d_in[7];
    const float* bv = (const float*)d_in[8];
    const float* Wo = (const float*)d_in[9];
    const float* bo = (const float*)d_in[10];
    float* out = (float*)d_out;

    float *pq, *pk, *pv, *pctx;
    cudaGetSymbolAddress((void**)&pq,   g_q);
    cudaGetSymbolAddress((void**)&pk,   g_k);
    cudaGetSymbolAddress((void**)&pv,   g_v);
    cudaGetSymbolAddress((void**)&pctx, g_ctx);

    cudaFuncSetAttribute(attn_kernel,
                         cudaFuncAttributeMaxDynamicSharedMemorySize,
                         (int)ATTN_SMEM);

    dim3 gg(ROWS / 128, DIN / 128, NB);
    group_gemm<<<gg, 256>>>(query,  Wq, bq, pq, SCALING);
    group_gemm<<<gg, 256>>>(key_in, Wk, bk, pk, 1.0f);
    group_gemm<<<gg, 256>>>(value,  Wv, bv, pv, 1.0f);

    dim3 ag(T_ / QT, B_ * H_);
    attn_kernel<<<ag, 256, ATTN_SMEM>>>(pq, pk, pv, pctx);

    group_gemm<<<gg, 256>>>(pctx, Wo, bo, out, 1.0f);
}

// round 2
// speedup vs baseline: 1.0493x; 1.0493x over previous
#include <cuda_runtime.h>
#include <math.h>

#define T_   1024
#define B_   8
#define E_   1024
#define H_   16
#define HD   64
#define NB   4
#define DIN  256
#define TOPK 16
#define ROWS (T_*B_)          // 8192
#define BE   (B_*E_)          // 8192
#define SCALING 0.125f        // 64^-0.5

// ---------- scratch (device globals; no runtime allocation) ----------
__device__ float g_q[ROWS * E_];
__device__ float g_k[ROWS * E_];
__device__ float g_v[ROWS * E_];
__device__ float g_ctx[ROWS * E_];

// =====================================================================
// Block-diagonal group GEMM (unchanged from R1)
// =====================================================================
__global__ void __launch_bounds__(256) group_gemm(
    const float* __restrict__ X, const float* __restrict__ W,
    const float* __restrict__ bias, float* __restrict__ Y, float scale)
{
    const int nb = blockIdx.z;
    const int m0 = blockIdx.x * 128;
    const int n0 = blockIdx.y * 128;
    const float* Wn = W + nb * DIN * DIN;

    __shared__ float As[8][128];
    __shared__ float Bs[8][128];

    const int tid = threadIdx.x;
    const int ty = tid >> 4;
    const int tx = tid & 15;

    const int arow = tid >> 1;
    const int akc  = (tid & 1) * 4;
    const int bkr  = tid >> 5;
    const int bcol = (tid & 31) * 4;

    const float* Xb = X + (long)m0 * E_ + nb * DIN;

    float acc[8][8];
#pragma unroll
    for (int i = 0; i < 8; i++)
#pragma unroll
        for (int j = 0; j < 8; j++) acc[i][j] = 0.0f;

    for (int k0 = 0; k0 < DIN; k0 += 8) {
        float4 a4 = *(const float4*)(Xb + (long)arow * E_ + k0 + akc);
        float4 b4 = *(const float4*)(Wn + (k0 + bkr) * DIN + n0 + bcol);
        As[akc + 0][arow] = a4.x;
        As[akc + 1][arow] = a4.y;
        As[akc + 2][arow] = a4.z;
        As[akc + 3][arow] = a4.w;
        *(float4*)&Bs[bkr][bcol] = b4;
        __syncthreads();

#pragma unroll
        for (int kk = 0; kk < 8; kk++) {
            float af[8], bf[8];
            *(float4*)(af)     = *(const float4*)&As[kk][ty * 8];
            *(float4*)(af + 4) = *(const float4*)&As[kk][ty * 8 + 4];
            *(float4*)(bf)     = *(const float4*)&Bs[kk][tx * 8];
            *(float4*)(bf + 4) = *(const float4*)&Bs[kk][tx * 8 + 4];
#pragma unroll
            for (int i = 0; i < 8; i++)
#pragma unroll
                for (int j = 0; j < 8; j++)
                    acc[i][j] = fmaf(af[i], bf[j], acc[i][j]);
        }
        __syncthreads();
    }

    float bj[8];
#pragma unroll
    for (int j = 0; j < 8; j++) bj[j] = bias[nb * DIN + n0 + tx * 8 + j];

#pragma unroll
    for (int i = 0; i < 8; i++) {
        const long row = m0 + ty * 8 + i;
        float* yp = Y + row * E_ + nb * DIN + n0 + tx * 8;
        float4 o0, o1;
        o0.x = (acc[i][0] + bj[0]) * scale;
        o0.y = (acc[i][1] + bj[1]) * scale;
        o0.z = (acc[i][2] + bj[2]) * scale;
        o0.w = (acc[i][3] + bj[3]) * scale;
        o1.x = (acc[i][4] + bj[4]) * scale;
        o1.y = (acc[i][5] + bj[5]) * scale;
        o1.z = (acc[i][6] + bj[6]) * scale;
        o1.w = (acc[i][7] + bj[7]) * scale;
        *(float4*)yp       = o0;
        *(float4*)(yp + 4) = o1;
    }
}

// =====================================================================
// Fused attention. One block = 32 queries x 1 batch-head, 256 threads.
// Score loop restructured: warp = 8q x 128k, lane = 8q x 4k, float4
// over d, q via warp-broadcast LDS. Accumulation order (d ascending)
// is bitwise identical to R1 -> identical top-k selection.
// =====================================================================
#define QT  32
#define KT  256
#define SP  1032   // padded score row stride (floats)
#define KSP 68     // padded k/q tile row stride (float4-aligned)

__global__ void __launch_bounds__(256) attn_kernel(
    const float* __restrict__ qg, const float* __restrict__ kg,
    const float* __restrict__ vg, float* __restrict__ ctxg)
{
    extern __shared__ float sm[];
    float* S    = sm;                    // QT*SP
    float* ks   = S + QT * SP;           // KT*KSP
    float* qs   = ks + KT * KSP;         // QT*KSP
    float* rmax = qs + QT * KSP;         // 32
    float* rsum = rmax + QT;             // 32
    float* tpp  = rsum + QT;             // 32*16 probs
    int*   tpi  = (int*)(tpp + QT * TOPK); // 32*16 indices

    const int tid = threadIdx.x;
    const int qt  = blockIdx.x;          // 0..31
    const int bh  = blockIdx.y;          // 0..127
    const int bb  = bh >> 4;             // batch
    const int hh  = bh & 15;             // head
    const long base = (long)bb * E_ + hh * HD;

    const int lane = tid & 31;
    const int w    = tid >> 5;           // warp 0..7

    // ---- load q tile (32 x 64) once ----
    for (int f = tid; f < QT * 16; f += 256) {
        int r = f >> 4, d4 = (f & 15) * 4;
        float4 v4 = *(const float4*)(qg + (long)(qt * QT + r) * BE + base + d4);
        *(float4*)&qs[r * KSP + d4] = v4;
    }

    // ---- scores: 32 x 1024, warp = 8q x 128k ----
    const int g = w >> 1;                // q group: rows g*8 .. g*8+7
    const int s = w & 1;                 // k half of the KT tile

    const float* kb0 = ks + (s * 128 + lane) * KSP;
    const float* qb  = qs + g * 8 * KSP;

    for (int kt = 0; kt < T_; kt += KT) {
        __syncthreads();
        for (int f = tid; f < KT * 16; f += 256) {
            int r = f >> 4, d4 = (f & 15) * 4;
            float4 v4 = *(const float4*)(kg + (long)(kt + r) * BE + base + d4);
            *(float4*)&ks[r * KSP + d4] = v4;
        }
        __syncthreads();

        float acc[8][4];
#pragma unroll
        for (int i = 0; i < 8; i++)
#pragma unroll
            for (int j = 0; j < 4; j++) acc[i][j] = 0.0f;

#pragma unroll 2
        for (int d = 0; d < HD; d += 4) {
            float4 k4[4];
#pragma unroll
            for (int j = 0; j < 4; j++)
                k4[j] = *(const float4*)(kb0 + j * 32 * KSP + d);
#pragma unroll
            for (int i = 0; i < 8; i++) {
                float4 q4 = *(const float4*)(qb + i * KSP + d);
#pragma unroll
                for (int j = 0; j < 4; j++) {
                    acc[i][j] = fmaf(q4.x, k4[j].x, acc[i][j]);
                    acc[i][j] = fmaf(q4.y, k4[j].y, acc[i][j]);
                    acc[i][j] = fmaf(q4.z, k4[j].z, acc[i][j]);
                    acc[i][j] = fmaf(q4.w, k4[j].w, acc[i][j]);
                }
            }
        }

#pragma unroll
        for (int i = 0; i < 8; i++)
#pragma unroll
            for (int j = 0; j < 4; j++)
                S[(g * 8 + i) * SP + kt + s * 128 + lane + 32 * j] = acc[i][j];
    }
    __syncthreads();

    // ---- softmax stats per row (warp w owns rows 4w..4w+3) ----
    for (int r = w * 4; r < w * 4 + 4; r++) {
        float m = -INFINITY;
#pragma unroll 8
        for (int t = 0; t < 32; t++) m = fmaxf(m, S[r * SP + lane + 32 * t]);
#pragma unroll
        for (int o = 16; o; o >>= 1) m = fmaxf(m, __shfl_xor_sync(~0u, m, o));
        float sum = 0.0f;
#pragma unroll 8
        for (int t = 0; t < 32; t++) sum += __expf(S[r * SP + lane + 32 * t] - m);
#pragma unroll
        for (int o = 16; o; o >>= 1) sum += __shfl_xor_sync(~0u, sum, o);
        if (lane == 0) { rmax[r] = m; rsum[r] = sum; }
    }
    __syncwarp();

    // ---- top-16 per row: warp argmax with lazy per-lane cached max ----
    for (int r = w * 4; r < w * 4 + 4; r++) {
        const float m = rmax[r];
        const float inv = 1.0f / rsum[r];
        float lmax = -INFINITY; int lpos = lane;
#pragma unroll 8
        for (int t = 0; t < 32; t++) {
            float v = S[r * SP + lane + 32 * t];
            if (v > lmax) { lmax = v; lpos = lane + 32 * t; }
        }
        for (int it = 0; it < TOPK; it++) {
            float bm = lmax; int bp = lpos;
#pragma unroll
            for (int o = 16; o; o >>= 1) {
                float m2 = __shfl_xor_sync(~0u, bm, o);
                int   p2 = __shfl_xor_sync(~0u, bp, o);
                if (m2 > bm || (m2 == bm && p2 < bp)) { bm = m2; bp = p2; }
            }
            if (lane == 0) {
                tpi[r * TOPK + it] = bp;
                tpp[r * TOPK + it] = __expf(bm - m) * inv;
            }
            if ((bp & 31) == lane) {   // winner lane removes + rescans its 32
                S[r * SP + bp] = -INFINITY;
                lmax = -INFINITY; lpos = lane;
#pragma unroll 8
                for (int t = 0; t < 32; t++) {
                    float v = S[r * SP + lane + 32 * t];
                    if (v > lmax) { lmax = v; lpos = lane + 32 * t; }
                }
            }
        }
    }
    __syncthreads();

    // ---- sparse ctx: 16-key gather per query row ----
    const int cr = tid >> 3;             // 0..31 query row
    const int d0 = (tid & 7) * 8;        // 0..56
    float c[8];
#pragma unroll
    for (int i = 0; i < 8; i++) c[i] = 0.0f;
#pragma unroll
    for (int i = 0; i < TOPK; i++) {
        const int   idx = tpi[cr * TOPK + i];
        const float p   = tpp[cr * TOPK + i];
        const float* vp = vg + (long)idx * BE + base + d0;
        float4 a  = *(const float4*)vp;
        float4 bq = *(const float4*)(vp + 4);
        c[0] = fmaf(p, a.x,  c[0]); c[1] = fmaf(p, a.y,  c[1]);
        c[2] = fmaf(p, a.z,  c[2]); c[3] = fmaf(p, a.w,  c[3]);
        c[4] = fmaf(p, bq.x, c[4]); c[5] = fmaf(p, bq.y, c[5]);
        c[6] = fmaf(p, bq.z, c[6]); c[7] = fmaf(p, bq.w, c[7]);
    }
    float* op = ctxg + (long)(qt * QT + cr) * BE + base + d0;
    *(float4*)op       = make_float4(c[0], c[1], c[2], c[3]);
    *(float4*)(op + 4) = make_float4(c[4], c[5], c[6], c[7]);
}

// =====================================================================
// launch
// =====================================================================
static const size_t ATTN_SMEM =
    (size_t)(QT * SP + KT * KSP + QT * KSP + QT + QT + QT * TOPK + QT * TOPK) * 4;

extern "C" void kernel_launch(void* const* d_in, const int* in_sizes, int n_in,
                              void* d_out, int out_size)
{
    const float* query  = (const float*)d_in[0];
    const float* key_in = (const float*)d_in[1];
    const float* value  = (const float*)d_in[2];
    const float* Wq = (const float*)d_in[3];
    const float* bq = (const float*)d_in[4];
    const float* Wk = (const float*)d_in[5];
    const float* bk = (const float*)d_in[6];
    const float* Wv = (const float*)d_in[7];
    const float* bv = (const float*)d_in[8];
    const float* Wo = (const float*)d_in[9];
    const float* bo = (const float*)d_in[10];
    float* out = (float*)d_out;

    float *pq, *pk, *pv, *pctx;
    cudaGetSymbolAddress((void**)&pq,   g_q);
    cudaGetSymbolAddress((void**)&pk,   g_k);
    cudaGetSymbolAddress((void**)&pv,   g_v);
    cudaGetSymbolAddress((void**)&pctx, g_ctx);

    cudaFuncSetAttribute(attn_kernel,
                         cudaFuncAttributeMaxDynamicSharedMemorySize,
                         (int)ATTN_SMEM);

    dim3 gg(ROWS / 128, DIN / 128, NB);
    group_gemm<<<gg, 256>>>(query,  Wq, bq, pq, SCALING);
    group_gemm<<<gg, 256>>>(key_in, Wk, bk, pk, 1.0f);
    group_gemm<<<gg, 256>>>(value,  Wv, bv, pv, 1.0f);

    dim3 ag(T_ / QT, B_ * H_);
    attn_kernel<<<ag, 256, ATTN_SMEM>>>(pq, pk, pv, pctx);

    group_gemm<<<gg, 256>>>(pctx, Wo, bo, out, 1.0f);
}

// round 3
// speedup vs baseline: 1.3881x; 1.3229x over previous
#include <cuda_runtime.h>
#include <math.h>

#define T_   1024
#define B_   8
#define E_   1024
#define H_   16
#define HD   64
#define NB   4
#define DIN  256
#define TOPK 16
#define ROWS (T_*B_)          // 8192
#define BE   (B_*E_)          // 8192
#define SCALING 0.125f        // 64^-0.5

// ---------- scratch (device globals; no runtime allocation) ----------
__device__ float g_q[ROWS * E_];
__device__ float g_k[ROWS * E_];
__device__ float g_v[ROWS * E_];
__device__ float g_ctx[ROWS * E_];

// =====================================================================
// Block-diagonal group GEMM (unchanged)
// =====================================================================
__global__ void __launch_bounds__(256) group_gemm(
    const float* __restrict__ X, const float* __restrict__ W,
    const float* __restrict__ bias, float* __restrict__ Y, float scale)
{
    const int nb = blockIdx.z;
    const int m0 = blockIdx.x * 128;
    const int n0 = blockIdx.y * 128;
    const float* Wn = W + nb * DIN * DIN;

    __shared__ float As[8][128];
    __shared__ float Bs[8][128];

    const int tid = threadIdx.x;
    const int ty = tid >> 4;
    const int tx = tid & 15;

    const int arow = tid >> 1;
    const int akc  = (tid & 1) * 4;
    const int bkr  = tid >> 5;
    const int bcol = (tid & 31) * 4;

    const float* Xb = X + (long)m0 * E_ + nb * DIN;

    float acc[8][8];
#pragma unroll
    for (int i = 0; i < 8; i++)
#pragma unroll
        for (int j = 0; j < 8; j++) acc[i][j] = 0.0f;

    for (int k0 = 0; k0 < DIN; k0 += 8) {
        float4 a4 = *(const float4*)(Xb + (long)arow * E_ + k0 + akc);
        float4 b4 = *(const float4*)(Wn + (k0 + bkr) * DIN + n0 + bcol);
        As[akc + 0][arow] = a4.x;
        As[akc + 1][arow] = a4.y;
        As[akc + 2][arow] = a4.z;
        As[akc + 3][arow] = a4.w;
        *(float4*)&Bs[bkr][bcol] = b4;
        __syncthreads();

#pragma unroll
        for (int kk = 0; kk < 8; kk++) {
            float af[8], bf[8];
            *(float4*)(af)     = *(const float4*)&As[kk][ty * 8];
            *(float4*)(af + 4) = *(const float4*)&As[kk][ty * 8 + 4];
            *(float4*)(bf)     = *(const float4*)&Bs[kk][tx * 8];
            *(float4*)(bf + 4) = *(const float4*)&Bs[kk][tx * 8 + 4];
#pragma unroll
            for (int i = 0; i < 8; i++)
#pragma unroll
                for (int j = 0; j < 8; j++)
                    acc[i][j] = fmaf(af[i], bf[j], acc[i][j]);
        }
        __syncthreads();
    }

    float bj[8];
#pragma unroll
    for (int j = 0; j < 8; j++) bj[j] = bias[nb * DIN + n0 + tx * 8 + j];

#pragma unroll
    for (int i = 0; i < 8; i++) {
        const long row = m0 + ty * 8 + i;
        float* yp = Y + row * E_ + nb * DIN + n0 + tx * 8;
        float4 o0, o1;
        o0.x = (acc[i][0] + bj[0]) * scale;
        o0.y = (acc[i][1] + bj[1]) * scale;
        o0.z = (acc[i][2] + bj[2]) * scale;
        o0.w = (acc[i][3] + bj[3]) * scale;
        o1.x = (acc[i][4] + bj[4]) * scale;
        o1.y = (acc[i][5] + bj[5]) * scale;
        o1.z = (acc[i][6] + bj[6]) * scale;
        o1.w = (acc[i][7] + bj[7]) * scale;
        *(float4*)yp       = o0;
        *(float4*)(yp + 4) = o1;
    }
}

// =====================================================================
// Fused attention. One block = 32 queries x 1 batch-head, 512 threads
// (16 warps). Score warp tile = 4q x 128k; per-score accumulation order
// identical to R2 (d ascending) -> identical top-k selection.
// Top-k: redux-based argmax, 4-way ILP scans, fused max pass.
// =====================================================================
#define QT  32
#define KT  256
#define SP  1032   // padded score row stride (floats)
#define KSP 68     // padded k/q tile row stride (float4-aligned)
#define NTH 512

// monotone map float->u32 (order preserving for finite floats)
__device__ __forceinline__ unsigned fmono(float f) {
    unsigned b = __float_as_uint(f);
    return (b & 0x80000000u) ? ~b : (b | 0x80000000u);
}
__device__ __forceinline__ float fdemono(unsigned m) {
    unsigned b = (m & 0x80000000u) ? (m & 0x7fffffffu) : ~m;
    return __uint_as_float(b);
}

__global__ void __launch_bounds__(NTH) attn_kernel(
    const float* __restrict__ qg, const float* __restrict__ kg,
    const float* __restrict__ vg, float* __restrict__ ctxg)
{
    extern __shared__ float sm[];
    float* S    = sm;                      // QT*SP
    float* ks   = S + QT * SP;             // KT*KSP
    float* qs   = ks + KT * KSP;           // QT*KSP
    float* tpp  = qs + QT * KSP;           // 32*16 probs
    int*   tpi  = (int*)(tpp + QT * TOPK); // 32*16 indices

    const int tid = threadIdx.x;
    const int qt  = blockIdx.x;            // 0..31
    const int bh  = blockIdx.y;            // 0..127
    const int bb  = bh >> 4;
    const int hh  = bh & 15;
    const long base = (long)bb * E_ + hh * HD;

    const int lane = tid & 31;
    const int w    = tid >> 5;             // warp 0..15

    // ---- load q tile (32 x 64) once ----
    for (int f = tid; f < QT * 16; f += NTH) {
        int r = f >> 4, d4 = (f & 15) * 4;
        float4 v4 = *(const float4*)(qg + (long)(qt * QT + r) * BE + base + d4);
        *(float4*)&qs[r * KSP + d4] = v4;
    }

    // ---- scores: 32 x 1024, warp = 4q x 128k ----
    const int g = w >> 1;                  // q group: rows g*4 .. g*4+3
    const int s = w & 1;                   // k half of the KT tile

    const float* kb0 = ks + (s * 128 + lane) * KSP;
    const float* qb  = qs + g * 4 * KSP;

    for (int kt = 0; kt < T_; kt += KT) {
        __syncthreads();
        for (int f = tid; f < KT * 16; f += NTH) {
            int r = f >> 4, d4 = (f & 15) * 4;
            float4 v4 = *(const float4*)(kg + (long)(kt + r) * BE + base + d4);
            *(float4*)&ks[r * KSP + d4] = v4;
        }
        __syncthreads();

        float acc[4][4];
#pragma unroll
        for (int i = 0; i < 4; i++)
#pragma unroll
            for (int j = 0; j < 4; j++) acc[i][j] = 0.0f;

#pragma unroll 4
        for (int d = 0; d < HD; d += 4) {
            float4 k4[4];
#pragma unroll
            for (int j = 0; j < 4; j++)
                k4[j] = *(const float4*)(kb0 + j * 32 * KSP + d);
#pragma unroll
            for (int i = 0; i < 4; i++) {
                float4 q4 = *(const float4*)(qb + i * KSP + d);
#pragma unroll
                for (int j = 0; j < 4; j++) {
                    acc[i][j] = fmaf(q4.x, k4[j].x, acc[i][j]);
                    acc[i][j] = fmaf(q4.y, k4[j].y, acc[i][j]);
                    acc[i][j] = fmaf(q4.z, k4[j].z, acc[i][j]);
                    acc[i][j] = fmaf(q4.w, k4[j].w, acc[i][j]);
                }
            }
        }

#pragma unroll
        for (int i = 0; i < 4; i++)
#pragma unroll
            for (int j = 0; j < 4; j++)
                S[(g * 4 + i) * SP + kt + s * 128 + lane + 32 * j] = acc[i][j];
    }
    __syncthreads();

    // ---- per-row: fused max/top-16 + softmax denominator ----
    // warp w owns rows 2w, 2w+1
    for (int r = w * 2; r < w * 2 + 2; r++) {
        const float* Sr = S + r * SP;

        // 4-chain (val,pos) scan; merge preserves (max val, min pos) exactly
        float lv0 = -INFINITY, lv1 = -INFINITY, lv2 = -INFINITY, lv3 = -INFINITY;
        int   lp0 = 0, lp1 = 0, lp2 = 0, lp3 = 0;
#pragma unroll
        for (int t = 0; t < 32; t += 4) {
            float v0 = Sr[lane + 32 * (t + 0)];
            float v1 = Sr[lane + 32 * (t + 1)];
            float v2 = Sr[lane + 32 * (t + 2)];
            float v3 = Sr[lane + 32 * (t + 3)];
            if (v0 > lv0) { lv0 = v0; lp0 = lane + 32 * (t + 0); }
            if (v1 > lv1) { lv1 = v1; lp1 = lane + 32 * (t + 1); }
            if (v2 > lv2) { lv2 = v2; lp2 = lane + 32 * (t + 2); }
            if (v3 > lv3) { lv3 = v3; lp3 = lane + 32 * (t + 3); }
        }
        float lmax = lv0; int lpos = lp0;
        if (lv1 > lmax || (lv1 == lmax && lp1 < lpos)) { lmax = lv1; lpos = lp1; }
        if (lv2 > lmax || (lv2 == lmax && lp2 < lpos)) { lmax = lv2; lpos = lp2; }
        if (lv3 > lmax || (lv3 == lmax && lp3 < lpos)) { lmax = lv3; lpos = lp3; }

        // iteration 0 argmax == row max
        unsigned kb = fmono(lmax);
        unsigned mk = __reduce_max_sync(0xffffffffu, kb);
        unsigned cp = (kb == mk) ? (unsigned)lpos : 0xffffffffu;
        unsigned bp = __reduce_min_sync(0xffffffffu, cp);
        const float m = fdemono(mk);     // row max

        // softmax denominator (4 partials + butterfly)
        float s0 = 0.f, s1 = 0.f, s2 = 0.f, s3 = 0.f;
#pragma unroll
        for (int t = 0; t < 32; t += 4) {
            s0 += __expf(Sr[lane + 32 * (t + 0)] - m);
            s1 += __expf(Sr[lane + 32 * (t + 1)] - m);
            s2 += __expf(Sr[lane + 32 * (t + 2)] - m);
            s3 += __expf(Sr[lane + 32 * (t + 3)] - m);
        }
        float sum = (s0 + s1) + (s2 + s3);
#pragma unroll
        for (int o = 16; o; o >>= 1) sum += __shfl_xor_sync(~0u, sum, o);
        const float inv = 1.0f / sum;

        if (lane == 0) { tpi[r * TOPK] = (int)bp; tpp[r * TOPK] = inv; }
        if ((bp & 31) == lane) {
            // winner lane removes + rescans its column (4-chain)
            ((float*)Sr)[bp] = -INFINITY;
            lv0 = lv1 = lv2 = lv3 = -INFINITY;
            lp0 = lp1 = lp2 = lp3 = 0;
#pragma unroll
            for (int t = 0; t < 32; t += 4) {
                float v0 = Sr[lane + 32 * (t + 0)];
                float v1 = Sr[lane + 32 * (t + 1)];
                float v2 = Sr[lane + 32 * (t + 2)];
                float v3 = Sr[lane + 32 * (t + 3)];
                if (v0 > lv0) { lv0 = v0; lp0 = lane + 32 * (t + 0); }
                if (v1 > lv1) { lv1 = v1; lp1 = lane + 32 * (t + 1); }
                if (v2 > lv2) { lv2 = v2; lp2 = lane + 32 * (t + 2); }
                if (v3 > lv3) { lv3 = v3; lp3 = lane + 32 * (t + 3); }
            }
            lmax = lv0; lpos = lp0;
            if (lv1 > lmax || (lv1 == lmax && lp1 < lpos)) { lmax = lv1; lpos = lp1; }
            if (lv2 > lmax || (lv2 == lmax && lp2 < lpos)) { lmax = lv2; lpos = lp2; }
            if (lv3 > lmax || (lv3 == lmax && lp3 < lpos)) { lmax = lv3; lpos = lp3; }
        }

        for (int it = 1; it < TOPK; it++) {
            kb = fmono(lmax);
            mk = __reduce_max_sync(0xffffffffu, kb);
            cp = (kb == mk) ? (unsigned)lpos : 0xffffffffu;
            bp = __reduce_min_sync(0xffffffffu, cp);
            if (lane == 0) {
                tpi[r * TOPK + it] = (int)bp;
                tpp[r * TOPK + it] = __expf(fdemono(mk) - m) * inv;
            }
            if ((bp & 31) == lane) {
                ((float*)Sr)[bp] = -INFINITY;
                lv0 = lv1 = lv2 = lv3 = -INFINITY;
                lp0 = lp1 = lp2 = lp3 = 0;
#pragma unroll
                for (int t = 0; t < 32; t += 4) {
                    float v0 = Sr[lane + 32 * (t + 0)];
                    float v1 = Sr[lane + 32 * (t + 1)];
                    float v2 = Sr[lane + 32 * (t + 2)];
                    float v3 = Sr[lane + 32 * (t + 3)];
                    if (v0 > lv0) { lv0 = v0; lp0 = lane + 32 * (t + 0); }
                    if (v1 > lv1) { lv1 = v1; lp1 = lane + 32 * (t + 1); }
                    if (v2 > lv2) { lv2 = v2; lp2 = lane + 32 * (t + 2); }
                    if (v3 > lv3) { lv3 = v3; lp3 = lane + 32 * (t + 3); }
                }
                lmax = lv0; lpos = lp0;
                if (lv1 > lmax || (lv1 == lmax && lp1 < lpos)) { lmax = lv1; lpos = lp1; }
                if (lv2 > lmax || (lv2 == lmax && lp2 < lpos)) { lmax = lv2; lpos = lp2; }
                if (lv3 > lmax || (lv3 == lmax && lp3 < lpos)) { lmax = lv3; lpos = lp3; }
            }
        }
    }
    __syncthreads();

    // ---- sparse ctx: 16-key gather per query row (512 threads) ----
    const int cr = tid >> 4;               // 0..31 query row
    const int d0 = (tid & 15) * 4;         // 0..60
    float c0 = 0.f, c1 = 0.f, c2 = 0.f, c3 = 0.f;
#pragma unroll
    for (int i = 0; i < TOPK; i++) {
        const int   idx = tpi[cr * TOPK + i];
        const float p   = tpp[cr * TOPK + i];
        float4 a = *(const float4*)(vg + (long)idx * BE + base + d0);
        c0 = fmaf(p, a.x, c0); c1 = fmaf(p, a.y, c1);
        c2 = fmaf(p, a.z, c2); c3 = fmaf(p, a.w, c3);
    }
    *(float4*)(ctxg + (long)(qt * QT + cr) * BE + base + d0) =
        make_float4(c0, c1, c2, c3);
}

// =====================================================================
// launch
// =====================================================================
static const size_t ATTN_SMEM =
    (size_t)(QT * SP + KT * KSP + QT * KSP + QT * TOPK + QT * TOPK) * 4;

extern "C" void kernel_launch(void* const* d_in, const int* in_sizes, int n_in,
                              void* d_out, int out_size)
{
    const float* query  = (const float*)d_in[0];
    const float* key_in = (const float*)d_in[1];
    const float* value  = (const float*)d_in[2];
    const float* Wq = (const float*)d_in[3];
    const float* bq = (const float*)d_in[4];
    const float* Wk = (const float*)d_in[5];
    const float* bk = (const float*)d_in[6];
    const float* Wv = (const float*)d_in[7];
    const float* bv = (const float*)d_in[8];
    const float* Wo = (const float*)d_in[9];
    const float* bo = (const float*)d_in[10];
    float* out = (float*)d_out;

    float *pq, *pk, *pv, *pctx;
    cudaGetSymbolAddress((void**)&pq,   g_q);
    cudaGetSymbolAddress((void**)&pk,   g_k);
    cudaGetSymbolAddress((void**)&pv,   g_v);
    cudaGetSymbolAddress((void**)&pctx, g_ctx);

    cudaFuncSetAttribute(attn_kernel,
                         cudaFuncAttributeMaxDynamicSharedMemorySize,
                         (int)ATTN_SMEM);

    dim3 gg(ROWS / 128, DIN / 128, NB);
    group_gemm<<<gg, 256>>>(query,  Wq, bq, pq, SCALING);
    group_gemm<<<gg, 256>>>(key_in, Wk, bk, pk, 1.0f);
    group_gemm<<<gg, 256>>>(value,  Wv, bv, pv, 1.0f);

    dim3 ag(T_ / QT, B_ * H_);
    attn_kernel<<<ag, NTH, ATTN_SMEM>>>(pq, pk, pv, pctx);

    group_gemm<<<gg, 256>>>(pctx, Wo, bo, out, 1.0f);
}

// round 4
// speedup vs baseline: 1.5472x; 1.1146x over previous
#include <cuda_runtime.h>
#include <math.h>

#define T_   1024
#define B_   8
#define E_   1024
#define H_   16
#define HD   64
#define NB   4
#define DIN  256
#define TOPK 16
#define ROWS (T_*B_)          // 8192
#define BE   (B_*E_)          // 8192
#define SCALING 0.125f        // 64^-0.5

// ---------- scratch (device globals; no runtime allocation) ----------
__device__ float g_q[ROWS * E_];
__device__ float g_k[ROWS * E_];
__device__ float g_v[ROWS * E_];
__device__ float g_ctx[ROWS * E_];

// =====================================================================
// Block-diagonal group GEMM (unchanged, at fp32 issue floor)
// =====================================================================
__global__ void __launch_bounds__(256) group_gemm(
    const float* __restrict__ X, const float* __restrict__ W,
    const float* __restrict__ bias, float* __restrict__ Y, float scale)
{
    const int nb = blockIdx.z;
    const int m0 = blockIdx.x * 128;
    const int n0 = blockIdx.y * 128;
    const float* Wn = W + nb * DIN * DIN;

    __shared__ float As[8][128];
    __shared__ float Bs[8][128];

    const int tid = threadIdx.x;
    const int ty = tid >> 4;
    const int tx = tid & 15;

    const int arow = tid >> 1;
    const int akc  = (tid & 1) * 4;
    const int bkr  = tid >> 5;
    const int bcol = (tid & 31) * 4;

    const float* Xb = X + (long)m0 * E_ + nb * DIN;

    float acc[8][8];
#pragma unroll
    for (int i = 0; i < 8; i++)
#pragma unroll
        for (int j = 0; j < 8; j++) acc[i][j] = 0.0f;

    for (int k0 = 0; k0 < DIN; k0 += 8) {
        float4 a4 = *(const float4*)(Xb + (long)arow * E_ + k0 + akc);
        float4 b4 = *(const float4*)(Wn + (k0 + bkr) * DIN + n0 + bcol);
        As[akc + 0][arow] = a4.x;
        As[akc + 1][arow] = a4.y;
        As[akc + 2][arow] = a4.z;
        As[akc + 3][arow] = a4.w;
        *(float4*)&Bs[bkr][bcol] = b4;
        __syncthreads();

#pragma unroll
        for (int kk = 0; kk < 8; kk++) {
            float af[8], bf[8];
            *(float4*)(af)     = *(const float4*)&As[kk][ty * 8];
            *(float4*)(af + 4) = *(const float4*)&As[kk][ty * 8 + 4];
            *(float4*)(bf)     = *(const float4*)&Bs[kk][tx * 8];
            *(float4*)(bf + 4) = *(const float4*)&Bs[kk][tx * 8 + 4];
#pragma unroll
            for (int i = 0; i < 8; i++)
#pragma unroll
                for (int j = 0; j < 8; j++)
                    acc[i][j] = fmaf(af[i], bf[j], acc[i][j]);
        }
        __syncthreads();
    }

    float bj[8];
#pragma unroll
    for (int j = 0; j < 8; j++) bj[j] = bias[nb * DIN + n0 + tx * 8 + j];

#pragma unroll
    for (int i = 0; i < 8; i++) {
        const long row = m0 + ty * 8 + i;
        float* yp = Y + row * E_ + nb * DIN + n0 + tx * 8;
        float4 o0, o1;
        o0.x = (acc[i][0] + bj[0]) * scale;
        o0.y = (acc[i][1] + bj[1]) * scale;
        o0.z = (acc[i][2] + bj[2]) * scale;
        o0.w = (acc[i][3] + bj[3]) * scale;
        o1.x = (acc[i][4] + bj[4]) * scale;
        o1.y = (acc[i][5] + bj[5]) * scale;
        o1.z = (acc[i][6] + bj[6]) * scale;
        o1.w = (acc[i][7] + bj[7]) * scale;
        *(float4*)yp       = o0;
        *(float4*)(yp + 4) = o1;
    }
}

// =====================================================================
// Fused attention. One block = 32 queries x 1 batch-head, 1024 threads
// (32 warps). Score compute: warps 0-15, identical tile/order to R3
// (bitwise-same scores). Top-k: 1 row/warp, per-lane top-4 register
// cache, redux argmax, rare exact refill fallback.
// =====================================================================
#define QT  32
#define KT  256
#define SP  1032   // padded score row stride (floats)
#define KSP 68     // padded k/q tile row stride (float4-aligned)
#define NTH 1024

// monotone map float->u32 (order preserving for finite floats)
__device__ __forceinline__ unsigned fmono(float f) {
    unsigned b = __float_as_uint(f);
    return (b & 0x80000000u) ? ~b : (b | 0x80000000u);
}
__device__ __forceinline__ float fdemono(unsigned m) {
    unsigned b = (m & 0x80000000u) ? (m & 0x7fffffffu) : ~m;
    return __uint_as_float(b);
}

__global__ void __launch_bounds__(NTH, 1) attn_kernel(
    const float* __restrict__ qg, const float* __restrict__ kg,
    const float* __restrict__ vg, float* __restrict__ ctxg)
{
    extern __shared__ float sm[];
    float* S    = sm;                      // QT*SP
    float* ks   = S + QT * SP;             // KT*KSP
    float* qs   = ks + KT * KSP;           // QT*KSP
    float* tpp  = qs + QT * KSP;           // 32*16 probs
    int*   tpi  = (int*)(tpp + QT * TOPK); // 32*16 indices

    const int tid = threadIdx.x;
    const int qt  = blockIdx.x;            // 0..31
    const int bh  = blockIdx.y;            // 0..127
    const int bb  = bh >> 4;
    const int hh  = bh & 15;
    const long base = (long)bb * E_ + hh * HD;

    const int lane = tid & 31;
    const int w    = tid >> 5;             // warp 0..31

    // ---- load q tile (32 x 64) once ----
    if (tid < QT * 16) {
        int r = tid >> 4, d4 = (tid & 15) * 4;
        float4 v4 = *(const float4*)(qg + (long)(qt * QT + r) * BE + base + d4);
        *(float4*)&qs[r * KSP + d4] = v4;
    }

    // ---- scores: 32 x 1024; warps 0-15 compute (4q x 128k each) ----
    const int g = w >> 1;                  // q group (valid for w<16)
    const int s = w & 1;                   // k half

    const float* kb0 = ks + (s * 128 + lane) * KSP;
    const float* qb  = qs + (g & 7) * 4 * KSP;

    for (int kt = 0; kt < T_; kt += KT) {
        __syncthreads();
        for (int f = tid; f < KT * 16; f += NTH) {
            int r = f >> 4, d4 = (f & 15) * 4;
            float4 v4 = *(const float4*)(kg + (long)(kt + r) * BE + base + d4);
            *(float4*)&ks[r * KSP + d4] = v4;
        }
        __syncthreads();

        if (w < 16) {
            float acc[4][4];
#pragma unroll
            for (int i = 0; i < 4; i++)
#pragma unroll
                for (int j = 0; j < 4; j++) acc[i][j] = 0.0f;

#pragma unroll 4
            for (int d = 0; d < HD; d += 4) {
                float4 k4[4];
#pragma unroll
                for (int j = 0; j < 4; j++)
                    k4[j] = *(const float4*)(kb0 + j * 32 * KSP + d);
#pragma unroll
                for (int i = 0; i < 4; i++) {
                    float4 q4 = *(const float4*)(qb + i * KSP + d);
#pragma unroll
                    for (int j = 0; j < 4; j++) {
                        acc[i][j] = fmaf(q4.x, k4[j].x, acc[i][j]);
                        acc[i][j] = fmaf(q4.y, k4[j].y, acc[i][j]);
                        acc[i][j] = fmaf(q4.z, k4[j].z, acc[i][j]);
                        acc[i][j] = fmaf(q4.w, k4[j].w, acc[i][j]);
                    }
                }
            }

#pragma unroll
            for (int i = 0; i < 4; i++)
#pragma unroll
                for (int j = 0; j < 4; j++)
                    S[(g * 4 + i) * SP + kt + s * 128 + lane + 32 * j] = acc[i][j];
        }
    }
    __syncthreads();

    // ---- per-row top-16 + softmax: warp w owns row w ----
    {
        float* Sr = S + w * SP;

        // build exact per-lane sorted top-4 cache (pos ascending scan;
        // strict > insertion keeps (max val, min pos) extraction order)
        float v0 = -INFINITY, v1 = -INFINITY, v2 = -INFINITY, v3 = -INFINITY;
        int   p0 = 0, p1 = 0, p2 = 0, p3 = 0;
#pragma unroll 8
        for (int t = 0; t < 32; t++) {
            float nv = Sr[lane + 32 * t]; int np = lane + 32 * t;
            if (nv > v3) {
                if (nv > v1) {
                    if (nv > v0) { v3=v2;p3=p2; v2=v1;p2=p1; v1=v0;p1=p0; v0=nv;p0=np; }
                    else         { v3=v2;p3=p2; v2=v1;p2=p1; v1=nv;p1=np; }
                } else {
                    if (nv > v2) { v3=v2;p3=p2; v2=nv;p2=np; }
                    else         { v3=nv;p3=np; }
                }
            }
        }
        int cnt = 4;

        // iteration 0: argmax == row max
        unsigned kb = fmono(v0);
        unsigned mk = __reduce_max_sync(0xffffffffu, kb);
        unsigned cp = (kb == mk) ? (unsigned)p0 : 0xffffffffu;
        unsigned bp = __reduce_min_sync(0xffffffffu, cp);
        const float m = fdemono(mk);

        // softmax denominator (structure identical to R3 -> bitwise-same)
        float s0 = 0.f, s1 = 0.f, s2 = 0.f, s3 = 0.f;
#pragma unroll
        for (int t = 0; t < 32; t += 4) {
            s0 += __expf(Sr[lane + 32 * (t + 0)] - m);
            s1 += __expf(Sr[lane + 32 * (t + 1)] - m);
            s2 += __expf(Sr[lane + 32 * (t + 2)] - m);
            s3 += __expf(Sr[lane + 32 * (t + 3)] - m);
        }
        float sum = (s0 + s1) + (s2 + s3);
#pragma unroll
        for (int o = 16; o; o >>= 1) sum += __shfl_xor_sync(~0u, sum, o);
        const float inv = 1.0f / sum;

        if (lane == 0) { tpi[w * TOPK] = (int)bp; tpp[w * TOPK] = inv; }
        if ((bp & 31) == lane) {
            Sr[bp] = -INFINITY;
            v0=v1;p0=p1; v1=v2;p1=p2; v2=v3;p2=p3; v3=-INFINITY;
            if (--cnt == 0) {
                v0=v1=v2=v3=-INFINITY; p0=p1=p2=p3=0;
                for (int t = 0; t < 32; t++) {
                    float nv = Sr[lane + 32 * t]; int np = lane + 32 * t;
                    if (nv > v3) {
                        if (nv > v1) {
                            if (nv > v0) { v3=v2;p3=p2; v2=v1;p2=p1; v1=v0;p1=p0; v0=nv;p0=np; }
                            else         { v3=v2;p3=p2; v2=v1;p2=p1; v1=nv;p1=np; }
                        } else {
                            if (nv > v2) { v3=v2;p3=p2; v2=nv;p2=np; }
                            else         { v3=nv;p3=np; }
                        }
                    }
                }
                cnt = 4;
            }
        }

        for (int it = 1; it < TOPK; it++) {
            kb = fmono(v0);
            mk = __reduce_max_sync(0xffffffffu, kb);
            cp = (kb == mk) ? (unsigned)p0 : 0xffffffffu;
            bp = __reduce_min_sync(0xffffffffu, cp);
            if (lane == 0) {
                tpi[w * TOPK + it] = (int)bp;
                tpp[w * TOPK + it] = __expf(fdemono(mk) - m) * inv;
            }
            if ((bp & 31) == lane) {
                Sr[bp] = -INFINITY;
                v0=v1;p0=p1; v1=v2;p1=p2; v2=v3;p2=p3; v3=-INFINITY;
                if (--cnt == 0) {
                    v0=v1=v2=v3=-INFINITY; p0=p1=p2=p3=0;
                    for (int t = 0; t < 32; t++) {
                        float nv = Sr[lane + 32 * t]; int np = lane + 32 * t;
                        if (nv > v3) {
                            if (nv > v1) {
                                if (nv > v0) { v3=v2;p3=p2; v2=v1;p2=p1; v1=v0;p1=p0; v0=nv;p0=np; }
                                else         { v3=v2;p3=p2; v2=v1;p2=p1; v1=nv;p1=np; }
                            } else {
                                if (nv > v2) { v3=v2;p3=p2; v2=nv;p2=np; }
                                else         { v3=nv;p3=np; }
                            }
                        }
                    }
                    cnt = 4;
                }
            }
        }
    }
    __syncthreads();

    // ---- sparse ctx: 16-key gather per query row (1024 threads) ----
    const int cr = w;                      // 0..31 query row
    const int d0 = lane * 2;               // 0..62
    float c0 = 0.f, c1 = 0.f;
#pragma unroll
    for (int i = 0; i < TOPK; i++) {
        const int   idx = tpi[cr * TOPK + i];
        const float p   = tpp[cr * TOPK + i];
        float2 a = *(const float2*)(vg + (long)idx * BE + base + d0);
        c0 = fmaf(p, a.x, c0); c1 = fmaf(p, a.y, c1);
    }
    *(float2*)(ctxg + (long)(qt * QT + cr) * BE + base + d0) = make_float2(c0, c1);
}

// =====================================================================
// launch
// =====================================================================
static const size_t ATTN_SMEM =
    (size_t)(QT * SP + KT * KSP + QT * KSP + QT * TOPK + QT * TOPK) * 4;

extern "C" void kernel_launch(void* const* d_in, const int* in_sizes, int n_in,
                              void* d_out, int out_size)
{
    const float* query  = (const float*)d_in[0];
    const float* key_in = (const float*)d_in[1];
    const float* value  = (const float*)d_in[2];
    const float* Wq = (const float*)d_in[3];
    const float* bq = (const float*)d_in[4];
    const float* Wk = (const float*)d_in[5];
    const float* bk = (const float*)d_in[6];
    const float* Wv = (const float*)d_in[7];
    const float* bv = (const float*)d_in[8];
    const float* Wo = (const float*)d_in[9];
    const float* bo = (const float*)d_in[10];
    float* out = (float*)d_out;

    float *pq, *pk, *pv, *pctx;
    cudaGetSymbolAddress((void**)&pq,   g_q);
    cudaGetSymbolAddress((void**)&pk,   g_k);
    cudaGetSymbolAddress((void**)&pv,   g_v);
    cudaGetSymbolAddress((void**)&pctx, g_ctx);

    cudaFuncSetAttribute(attn_kernel,
                         cudaFuncAttributeMaxDynamicSharedMemorySize,
                         (int)ATTN_SMEM);

    dim3 gg(ROWS / 128, DIN / 128, NB);
    group_gemm<<<gg, 256>>>(query,  Wq, bq, pq, SCALING);
    group_gemm<<<gg, 256>>>(key_in, Wk, bk, pk, 1.0f);
    group_gemm<<<gg, 256>>>(value,  Wv, bv, pv, 1.0f);

    dim3 ag(T_ / QT, B_ * H_);
    attn_kernel<<<ag, NTH, ATTN_SMEM>>>(pq, pk, pv, pctx);

    group_gemm<<<gg, 256>>>(pctx, Wo, bo, out, 1.0f);
}